// round 11
// baseline (speedup 1.0000x reference)
#include <cuda_runtime.h>
#include <cuda_bf16.h>
#include <cstdint>

// Problem constants
#define BATCH 2
#define HEADS 16
#define SEQ   2048
#define DMODEL 1024
#define DHEAD 64
#define OUT_ELEMS (BATCH * SEQ * DMODEL)  // 4,194,304

// ---------------- scratch (device globals: allocation-free) ----------------
__device__ float g_q[BATCH * HEADS * SEQ * DHEAD];   // [b,h,s,d]
__device__ float g_k[BATCH * HEADS * SEQ * DHEAD];
__device__ float g_v[BATCH * HEADS * SEQ * DHEAD];
__device__ float g_ctx[BATCH * SEQ * DMODEL];        // [b,s,D]
__device__ float g_inv[BATCH * HEADS * SEQ];         // 1/l per (b,h,q)

// ---------------- helpers ----------------
__device__ __forceinline__ uint32_t f2tf32(float x) {
    uint32_t r;
    asm("cvt.rna.tf32.f32 %0, %1;" : "=r"(r) : "f"(x));
    return r;
}
__device__ __forceinline__ float ex2f(float x) {
    float r;
    asm("ex2.approx.f32 %0, %1;" : "=f"(r) : "f"(x));
    return r;
}

__device__ __forceinline__ void mma_tf32(float c[4],
                                         uint32_t a0, uint32_t a1, uint32_t a2, uint32_t a3,
                                         uint32_t b0, uint32_t b1) {
    asm volatile(
        "mma.sync.aligned.m16n8k8.row.col.f32.tf32.tf32.f32 "
        "{%0,%1,%2,%3}, {%4,%5,%6,%7}, {%8,%9}, {%0,%1,%2,%3};"
        : "+f"(c[0]), "+f"(c[1]), "+f"(c[2]), "+f"(c[3])
        : "r"(a0), "r"(a1), "r"(a2), "r"(a3), "r"(b0), "r"(b1));
}

// pack order within an 8-wide k-group: word positions hold cols [0,4,1,5,2,6,3,7]
__device__ __forceinline__ void pack8(const float4& f0, const float4& f1,
                                      uint4& o0, uint4& o1) {
    o0.x = f2tf32(f0.x); o0.y = f2tf32(f1.x); o0.z = f2tf32(f0.y); o0.w = f2tf32(f1.y);
    o1.x = f2tf32(f0.z); o1.y = f2tf32(f1.z); o1.z = f2tf32(f0.w); o1.w = f2tf32(f1.w);
}

// ================= GEMM core: double-buffered SMEM, 1 sync/chunk =============
#define GBS 136

template <int MODE_IS_QKV>
__device__ __forceinline__ void gemm_body(const float* __restrict__ X,
                                          const float* __restrict__ W,
                                          const float* __restrict__ bias,
                                          float* __restrict__ Yh,
                                          int m0, int n0) {
    __shared__ uint32_t As[2][2048];       // [stage][g2][m][8 packed]
    __shared__ uint32_t Bs[2][16 * GBS];   // [stage][k][n]

    const int tid = threadIdx.x;
    const int w = tid >> 5, lane = tid & 31;
    const int wm = w & 1, wn = w >> 1;
    const int g = lane >> 2, tg = lane & 3;

    const int ar = tid & 127, ag2 = tid >> 7;
    const int br = tid >> 4, bc = (tid & 15) * 8;

    float acc[4][4][4];
#pragma unroll
    for (int mt = 0; mt < 4; mt++)
#pragma unroll
        for (int nt = 0; nt < 4; nt++)
#pragma unroll
            for (int i = 0; i < 4; i++) acc[mt][nt][i] = 0.f;

    // prologue: load + store chunk 0 into stage 0
    {
        float4 a0r = *reinterpret_cast<const float4*>(&X[(size_t)(m0 + ar) * DMODEL + ag2 * 8]);
        float4 a1r = *reinterpret_cast<const float4*>(&X[(size_t)(m0 + ar) * DMODEL + ag2 * 8 + 4]);
        float4 b0r = *reinterpret_cast<const float4*>(&W[(size_t)br * DMODEL + n0 + bc]);
        float4 b1r = *reinterpret_cast<const float4*>(&W[(size_t)br * DMODEL + n0 + bc + 4]);
        uint4 p0, p1;
        pack8(a0r, a1r, p0, p1);
        *reinterpret_cast<uint4*>(&As[0][ag2 * 1024 + ar * 8]) = p0;
        *reinterpret_cast<uint4*>(&As[0][ag2 * 1024 + ar * 8 + 4]) = p1;
        uint4 t0 = {f2tf32(b0r.x), f2tf32(b0r.y), f2tf32(b0r.z), f2tf32(b0r.w)};
        uint4 t1 = {f2tf32(b1r.x), f2tf32(b1r.y), f2tf32(b1r.z), f2tf32(b1r.w)};
        *reinterpret_cast<uint4*>(&Bs[0][br * GBS + bc]) = t0;
        *reinterpret_cast<uint4*>(&Bs[0][br * GBS + bc + 4]) = t1;
    }

#pragma unroll 1
    for (int c = 0; c < 64; c++) {
        const int st = c & 1;
        __syncthreads();

        float4 a0r, a1r, b0r, b1r;
        const bool more = (c + 1 < 64);
        if (more) {
            int k0 = (c + 1) * 16;
            a0r = *reinterpret_cast<const float4*>(&X[(size_t)(m0 + ar) * DMODEL + k0 + ag2 * 8]);
            a1r = *reinterpret_cast<const float4*>(&X[(size_t)(m0 + ar) * DMODEL + k0 + ag2 * 8 + 4]);
            b0r = *reinterpret_cast<const float4*>(&W[(size_t)(k0 + br) * DMODEL + n0 + bc]);
            b1r = *reinterpret_cast<const float4*>(&W[(size_t)(k0 + br) * DMODEL + n0 + bc + 4]);
        }

        const uint32_t* Ac = As[st];
        const uint32_t* Bc = Bs[st];
#pragma unroll
        for (int kg = 0; kg < 2; kg++) {
            uint32_t a[4][4], bf[4][2];
#pragma unroll
            for (int mt = 0; mt < 4; mt++) {
                int mm = wm * 64 + mt * 16 + g;
                uint2 lo = *reinterpret_cast<const uint2*>(&Ac[kg * 1024 + mm * 8 + 2 * tg]);
                uint2 hi = *reinterpret_cast<const uint2*>(&Ac[kg * 1024 + (mm + 8) * 8 + 2 * tg]);
                a[mt][0] = lo.x; a[mt][1] = hi.x; a[mt][2] = lo.y; a[mt][3] = hi.y;
            }
#pragma unroll
            for (int nt = 0; nt < 4; nt++) {
                int nn = wn * 32 + nt * 8 + g;
                bf[nt][0] = Bc[(kg * 8 + tg) * GBS + nn];
                bf[nt][1] = Bc[(kg * 8 + tg + 4) * GBS + nn];
            }
#pragma unroll
            for (int mt = 0; mt < 4; mt++)
#pragma unroll
                for (int nt = 0; nt < 4; nt++)
                    mma_tf32(acc[mt][nt], a[mt][0], a[mt][1], a[mt][2], a[mt][3],
                             bf[nt][0], bf[nt][1]);
        }

        if (more) {
            const int st2 = st ^ 1;
            uint4 p0, p1;
            pack8(a0r, a1r, p0, p1);
            *reinterpret_cast<uint4*>(&As[st2][ag2 * 1024 + ar * 8]) = p0;
            *reinterpret_cast<uint4*>(&As[st2][ag2 * 1024 + ar * 8 + 4]) = p1;
            uint4 t0 = {f2tf32(b0r.x), f2tf32(b0r.y), f2tf32(b0r.z), f2tf32(b0r.w)};
            uint4 t1 = {f2tf32(b1r.x), f2tf32(b1r.y), f2tf32(b1r.z), f2tf32(b1r.w)};
            *reinterpret_cast<uint4*>(&Bs[st2][br * GBS + bc]) = t0;
            *reinterpret_cast<uint4*>(&Bs[st2][br * GBS + bc + 4]) = t1;
        }
    }

#pragma unroll
    for (int nt = 0; nt < 4; nt++) {
        int n = n0 + wn * 32 + nt * 8 + tg * 2;
        float bi0 = __ldg(&bias[n]), bi1 = __ldg(&bias[n + 1]);
#pragma unroll
        for (int mt = 0; mt < 4; mt++) {
#pragma unroll
            for (int half = 0; half < 2; half++) {
                int m = m0 + wm * 64 + mt * 16 + g + half * 8;
                float v0 = acc[mt][nt][half * 2 + 0] + bi0;
                float v1 = acc[mt][nt][half * 2 + 1] + bi1;
                if (MODE_IS_QKV) {
                    int b = m >> 11, s = m & 2047;
                    int h = n >> 6, d = n & 63;
                    size_t base = (((size_t)(b * HEADS + h) * SEQ + s) * DHEAD);
                    Yh[base + d] = v0;
                    Yh[base + d + 1] = v1;
                } else {
                    Yh[(size_t)m * DMODEL + n] = v0;
                    Yh[(size_t)m * DMODEL + n + 1] = v1;
                }
            }
        }
    }
}

// fused Q/K/V projections: blockIdx.z selects which
__global__ __launch_bounds__(256, 2) void gemm_qkv_kernel(
    const float* __restrict__ query, const float* __restrict__ key_,
    const float* __restrict__ value,
    const float* __restrict__ Wq, const float* __restrict__ bq,
    const float* __restrict__ Wk, const float* __restrict__ bk,
    const float* __restrict__ Wv, const float* __restrict__ bv) {
    const int mode = blockIdx.z;
    const float* X = (mode == 0) ? query : (mode == 1) ? key_ : value;
    const float* W = (mode == 0) ? Wq : (mode == 1) ? Wk : Wv;
    const float* bias = (mode == 0) ? bq : (mode == 1) ? bk : bv;
    float* Yh = (mode == 0) ? g_q : (mode == 1) ? g_k : g_v;
    gemm_body<1>(X, W, bias, Yh, blockIdx.y * 128, blockIdx.x * 128);
}

// ======== fused: output projection (blocks 0..255) + attn rescale (256..1279) =
__global__ __launch_bounds__(256, 2) void gemm_o_rescale_kernel(
    const float* __restrict__ Wo, const float* __restrict__ bo,
    float* __restrict__ out, float* __restrict__ attn) {
    if (blockIdx.x < 256) {
        gemm_body<0>(g_ctx, Wo, bo, out, ((int)blockIdx.x >> 3) * 128,
                     ((int)blockIdx.x & 7) * 128);
        return;
    }
    // rescale: 1024 blocks, each normalizes 64 attn rows (64 x 2048 floats)
    __shared__ float sinv[64];
    const int rid = blockIdx.x - 256;
    const int bh = rid >> 5;
    const int q0 = (rid & 31) * 64;
    const int tid = threadIdx.x;
    float* arow = attn + (size_t)bh * SEQ * SEQ + (size_t)q0 * SEQ;
    if (tid < 64) sinv[tid] = g_inv[bh * SEQ + q0 + tid];
    __syncthreads();
    float4* af4 = reinterpret_cast<float4*>(arow);
#pragma unroll 4
    for (int j = 0; j < 128; j++) {
        int id = j * 256 + tid;
        int r = id >> 9, cc = id & 511;
        float I = sinv[r];
        float4 f = af4[r * 512 + cc];
        f.x *= I; f.y *= I; f.z *= I; f.w *= I;
        af4[r * 512 + cc] = f;
    }
}

// ======== one-pass attention (R10 config), no rescale epilogue ==========
// grid (SEQ/64, HEADS, BATCH), 256 threads, warps 2(m)x4(n), CH=128.
// Q scaled by 0.125*log2(e); P' = exp2(S). Unnormalized attn write; 1/l
// stored to g_inv for the fused rescale kernel; ctx normalized in-kernel.
#define QT 64
#define CH 128
#define QSs 72
#define KSs 72
#define VSs 72
#define PSs 136
// words: Qs 64*72=4608; Ks 128*72=9216 (aliased as Ps 64*136=8704); Vs 9216; stats 320
#define ATTN_SMEM_U32 (4608 + 9216 + 9216 + 320)

__global__ __launch_bounds__(256, 2) void attn_kernel(float* __restrict__ attn_out) {
    extern __shared__ uint32_t smem_u[];
    uint32_t* Qs = smem_u;
    uint32_t* Ks = Qs + 4608;
    uint32_t* Vs = Ks + 9216;
    float* lbuf = reinterpret_cast<float*>(Vs + 9216);   // [4][64]
    float* smI = lbuf + 256;                             // [64]

    const int tid = threadIdx.x;
    const int w = tid >> 5, lane = tid & 31;
    const int wm = w & 1, wn = w >> 1;
    const int g = lane >> 2, tg = lane & 3;

    const int q0 = blockIdx.x * QT;
    const int h = blockIdx.y, b = blockIdx.z;
    const int bh = b * HEADS + h;

    const float* qh = g_q + (size_t)bh * SEQ * DHEAD;
    const float* kh = g_k + (size_t)bh * SEQ * DHEAD;
    const float* vh = g_v + (size_t)bh * SEQ * DHEAD;
    float* arow = attn_out + (size_t)bh * SEQ * SEQ + (size_t)q0 * SEQ;

    // ---- stage Q (packed, scale = 0.125 * log2 e) ----
    const float QSC = 0.125f * 1.4426950408889634f;
#pragma unroll
    for (int j = 0; j < 2; j++) {
        int id = j * 256 + tid;
        int r = id >> 3, grp = id & 7;
        float4 f0 = *reinterpret_cast<const float4*>(&qh[(size_t)(q0 + r) * DHEAD + grp * 8]);
        float4 f1 = *reinterpret_cast<const float4*>(&qh[(size_t)(q0 + r) * DHEAD + grp * 8 + 4]);
        f0.x *= QSC; f0.y *= QSC; f0.z *= QSC; f0.w *= QSC;
        f1.x *= QSC; f1.y *= QSC; f1.z *= QSC; f1.w *= QSC;
        uint4 p0, p1;
        pack8(f0, f1, p0, p1);
        *reinterpret_cast<uint4*>(&Qs[r * QSs + grp * 8]) = p0;
        *reinterpret_cast<uint4*>(&Qs[r * QSs + grp * 8 + 4]) = p1;
    }
    __syncthreads();

    const int rA0 = wm * 32 + g;    // + mt*16, + 8 for high half
    const int kc0 = wn * 32;        // this warp's 32-key slice
    const int vc0 = wn * 16;

    uint32_t* Ps = Ks;              // packed P' tile aliases K buffer
    const int pk0 = ((2 * tg) & 3) * 2 + ((2 * tg) >> 2);
    const int pk1 = ((2 * tg + 1) & 3) * 2 + ((2 * tg + 1) >> 2);

    float lacc[4];
#pragma unroll
    for (int i = 0; i < 4; i++) lacc[i] = 0.f;
    float oacc[2][2][4];
#pragma unroll
    for (int mt = 0; mt < 2; mt++)
#pragma unroll
        for (int nt = 0; nt < 2; nt++)
#pragma unroll
            for (int i = 0; i < 4; i++) oacc[mt][nt][i] = 0.f;

    for (int c = 0; c < SEQ / CH; c++) {
        const int kb = c * CH;
        // stage K (packed) + V (tf32)
#pragma unroll
        for (int j = 0; j < 4; j++) {
            int id = j * 256 + tid;
            int r = id >> 3, grp = id & 7;
            float4 f0 = *reinterpret_cast<const float4*>(&kh[(size_t)(kb + r) * DHEAD + grp * 8]);
            float4 f1 = *reinterpret_cast<const float4*>(&kh[(size_t)(kb + r) * DHEAD + grp * 8 + 4]);
            uint4 p0, p1;
            pack8(f0, f1, p0, p1);
            *reinterpret_cast<uint4*>(&Ks[r * KSs + grp * 8]) = p0;
            *reinterpret_cast<uint4*>(&Ks[r * KSs + grp * 8 + 4]) = p1;
        }
#pragma unroll
        for (int j = 0; j < 8; j++) {
            int id = j * 256 + tid;
            int r = id >> 4, c4 = (id & 15) * 4;
            float4 v4 = *reinterpret_cast<const float4*>(&vh[(size_t)(kb + r) * DHEAD + c4]);
            uint4 tv = {f2tf32(v4.x), f2tf32(v4.y), f2tf32(v4.z), f2tf32(v4.w)};
            *reinterpret_cast<uint4*>(&Vs[r * VSs + c4]) = tv;
        }
        __syncthreads();

        // S = Q @ K^T
        float sacc[2][4][4];
#pragma unroll
        for (int mt = 0; mt < 2; mt++)
#pragma unroll
            for (int nt = 0; nt < 4; nt++)
#pragma unroll
                for (int i = 0; i < 4; i++) sacc[mt][nt][i] = 0.f;
#pragma unroll
        for (int s = 0; s < 8; s++) {
            uint32_t a[2][4];
#pragma unroll
            for (int mt = 0; mt < 2; mt++) {
                int rr = rA0 + mt * 16;
                uint2 lo = *reinterpret_cast<uint2*>(&Qs[rr * QSs + s * 8 + 2 * tg]);
                uint2 hi = *reinterpret_cast<uint2*>(&Qs[(rr + 8) * QSs + s * 8 + 2 * tg]);
                a[mt][0] = lo.x; a[mt][1] = hi.x; a[mt][2] = lo.y; a[mt][3] = hi.y;
            }
#pragma unroll
            for (int nt = 0; nt < 4; nt++) {
                int kr = kc0 + nt * 8 + g;
                uint2 bb = *reinterpret_cast<uint2*>(&Ks[kr * KSs + s * 8 + 2 * tg]);
                mma_tf32(sacc[0][nt], a[0][0], a[0][1], a[0][2], a[0][3], bb.x, bb.y);
                mma_tf32(sacc[1][nt], a[1][0], a[1][1], a[1][2], a[1][3], bb.x, bb.y);
            }
        }
        __syncthreads();   // K reads done before Ps (=Ks) is overwritten

        // P' = exp2(S) : row sums, unnormalized attn write, pack to Ps
#pragma unroll
        for (int mt = 0; mt < 2; mt++) {
            int r0_ = rA0 + mt * 16, r1_ = r0_ + 8;
#pragma unroll
            for (int nt = 0; nt < 4; nt++) {
                int gbase = kc0 + nt * 8;
                float p0 = ex2f(sacc[mt][nt][0]);
                float p1 = ex2f(sacc[mt][nt][1]);
                float p2 = ex2f(sacc[mt][nt][2]);
                float p3 = ex2f(sacc[mt][nt][3]);
                lacc[mt * 2]     += p0 + p1;
                lacc[mt * 2 + 1] += p2 + p3;
                float2 w0 = {p0, p1}, w1 = {p2, p3};
                *reinterpret_cast<float2*>(&arow[(size_t)r0_ * SEQ + kb + gbase + 2 * tg]) = w0;
                *reinterpret_cast<float2*>(&arow[(size_t)r1_ * SEQ + kb + gbase + 2 * tg]) = w1;
                Ps[r0_ * PSs + gbase + pk0] = f2tf32(p0);
                Ps[r0_ * PSs + gbase + pk1] = f2tf32(p1);
                Ps[r1_ * PSs + gbase + pk0] = f2tf32(p2);
                Ps[r1_ * PSs + gbase + pk1] = f2tf32(p3);
            }
        }
        __syncthreads();

        // O' += P' @ V
#pragma unroll
        for (int kg = 0; kg < 16; kg++) {
            uint32_t pa[2][4];
#pragma unroll
            for (int mt = 0; mt < 2; mt++) {
                int rr = rA0 + mt * 16;
                uint2 lo = *reinterpret_cast<uint2*>(&Ps[rr * PSs + kg * 8 + 2 * tg]);
                uint2 hi = *reinterpret_cast<uint2*>(&Ps[(rr + 8) * PSs + kg * 8 + 2 * tg]);
                pa[mt][0] = lo.x; pa[mt][1] = hi.x; pa[mt][2] = lo.y; pa[mt][3] = hi.y;
            }
#pragma unroll
            for (int nt = 0; nt < 2; nt++) {
                int vcol = vc0 + nt * 8 + g;
                uint32_t b0 = Vs[(kg * 8 + tg) * VSs + vcol];
                uint32_t b1 = Vs[(kg * 8 + tg + 4) * VSs + vcol];
                mma_tf32(oacc[0][nt], pa[0][0], pa[0][1], pa[0][2], pa[0][3], b0, b1);
                mma_tf32(oacc[1][nt], pa[1][0], pa[1][1], pa[1][2], pa[1][3], b0, b1);
            }
        }
        __syncthreads();   // Ps reads done before next chunk's K staging
    }

    // ---- reduce l: quad shuffle then across 4 n-warps via smem ----
#pragma unroll
    for (int i = 0; i < 4; i++) {
        lacc[i] += __shfl_xor_sync(0xffffffffu, lacc[i], 1);
        lacc[i] += __shfl_xor_sync(0xffffffffu, lacc[i], 2);
    }
    if (tg == 0) {
#pragma unroll
        for (int mt = 0; mt < 2; mt++)
#pragma unroll
            for (int hf = 0; hf < 2; hf++)
                lbuf[wn * 64 + rA0 + mt * 16 + hf * 8] = lacc[mt * 2 + hf];
    }
    __syncthreads();
    if (tid < 64) {
        float inv = 1.f / (lbuf[tid] + lbuf[64 + tid] + lbuf[128 + tid] + lbuf[192 + tid]);
        smI[tid] = inv;
        g_inv[bh * SEQ + q0 + tid] = inv;   // for the fused rescale kernel
    }
    __syncthreads();

    // ---- write context O = O'/l (head-interleaved) ----
#pragma unroll
    for (int mt = 0; mt < 2; mt++) {
        int r0_ = rA0 + mt * 16, r1_ = r0_ + 8;
        float I0 = smI[r0_], I1 = smI[r1_];
#pragma unroll
        for (int nt = 0; nt < 2; nt++) {
            int cc = h * DHEAD + vc0 + nt * 8 + tg * 2;
            float2 o0 = {oacc[mt][nt][0] * I0, oacc[mt][nt][1] * I0};
            float2 o1 = {oacc[mt][nt][2] * I1, oacc[mt][nt][3] * I1};
            *reinterpret_cast<float2*>(&g_ctx[((size_t)(b * SEQ + q0 + r0_)) * DMODEL + cc]) = o0;
            *reinterpret_cast<float2*>(&g_ctx[((size_t)(b * SEQ + q0 + r1_)) * DMODEL + cc]) = o1;
        }
    }
}

// ---------------- launch ----------------
extern "C" void kernel_launch(void* const* d_in, const int* in_sizes, int n_in,
                              void* d_out, int out_size) {
    const float* query = (const float*)d_in[0];
    const float* key   = (const float*)d_in[1];
    const float* value = (const float*)d_in[2];
    const float* Wq = (const float*)d_in[3];
    const float* bq = (const float*)d_in[4];
    const float* Wk = (const float*)d_in[5];
    const float* bk = (const float*)d_in[6];
    const float* Wv = (const float*)d_in[7];
    const float* bv = (const float*)d_in[8];
    const float* Wo = (const float*)d_in[9];
    const float* bo = (const float*)d_in[10];

    float* out = (float*)d_out;
    float* attn = out + OUT_ELEMS;

    static bool attr_set = false;
    if (!attr_set) {
        cudaFuncSetAttribute(attn_kernel, cudaFuncAttributeMaxDynamicSharedMemorySize,
                             ATTN_SMEM_U32 * 4);
        attr_set = true;
    }

    dim3 ggrid(DMODEL / 128, (BATCH * SEQ) / 128, 3);
    gemm_qkv_kernel<<<ggrid, 256>>>(query, key, value, Wq, bq, Wk, bk, Wv, bv);

    dim3 agrid(SEQ / QT, HEADS, BATCH);
    attn_kernel<<<agrid, 256, ATTN_SMEM_U32 * 4>>>(attn);

    gemm_o_rescale_kernel<<<1280, 256>>>(Wo, bo, out, attn);
}

// round 13
// speedup vs baseline: 1.1108x; 1.1108x over previous
#include <cuda_runtime.h>
#include <cuda_bf16.h>
#include <cstdint>

// Problem constants
#define BATCH 2
#define HEADS 16
#define SEQ   2048
#define DMODEL 1024
#define DHEAD 64
#define OUT_ELEMS (BATCH * SEQ * DMODEL)  // 4,194,304

// ---------------- scratch (device globals: allocation-free) ----------------
// g_q: tf32 bits, pre-scaled by 0.125*log2(e), k-pair-packed within 8-groups
// g_k: tf32 bits, k-pair-packed within 8-groups
// g_v: tf32-rounded floats, plain layout
__device__ uint32_t g_q[BATCH * HEADS * SEQ * DHEAD];
__device__ uint32_t g_k[BATCH * HEADS * SEQ * DHEAD];
__device__ float    g_v[BATCH * HEADS * SEQ * DHEAD];
__device__ float    g_ctx[BATCH * SEQ * DMODEL];

#define QSC (0.125f * 1.4426950408889634f)

// ---------------- helpers ----------------
__device__ __forceinline__ uint32_t f2tf32(float x) {
    uint32_t r;
    asm("cvt.rna.tf32.f32 %0, %1;" : "=r"(r) : "f"(x));
    return r;
}
__device__ __forceinline__ float ex2f(float x) {
    float r;
    asm("ex2.approx.f32 %0, %1;" : "=f"(r) : "f"(x));
    return r;
}

__device__ __forceinline__ void mma_tf32(float c[4],
                                         uint32_t a0, uint32_t a1, uint32_t a2, uint32_t a3,
                                         uint32_t b0, uint32_t b1) {
    asm volatile(
        "mma.sync.aligned.m16n8k8.row.col.f32.tf32.tf32.f32 "
        "{%0,%1,%2,%3}, {%4,%5,%6,%7}, {%8,%9}, {%0,%1,%2,%3};"
        : "+f"(c[0]), "+f"(c[1]), "+f"(c[2]), "+f"(c[3])
        : "r"(a0), "r"(a1), "r"(a2), "r"(a3), "r"(b0), "r"(b1));
}

// pack order within an 8-wide k-group: word positions hold cols [0,4,1,5,2,6,3,7]
__device__ __forceinline__ void pack8(const float4& f0, const float4& f1,
                                      uint4& o0, uint4& o1) {
    o0.x = f2tf32(f0.x); o0.y = f2tf32(f1.x); o0.z = f2tf32(f0.y); o0.w = f2tf32(f1.y);
    o1.x = f2tf32(f0.z); o1.y = f2tf32(f1.z); o1.z = f2tf32(f0.w); o1.w = f2tf32(f1.w);
}

__device__ __forceinline__ void cp16(uint32_t smem_addr, const void* gptr) {
    asm volatile("cp.async.cg.shared.global [%0], [%1], 16;"
                 :: "r"(smem_addr), "l"(gptr));
}
#define CP_COMMIT() asm volatile("cp.async.commit_group;" ::: "memory")
#define CP_WAIT0()  asm volatile("cp.async.wait_group 0;" ::: "memory")

// ================= GEMM core: double-buffered SMEM, 1 sync/chunk =============
// MODE: 0=Q (packed+scaled), 1=K (packed), 2=V (rounded), 3=output (plain)
#define GBS 136

template <int MODE>
__device__ __forceinline__ void gemm_body(const float* __restrict__ X,
                                          const float* __restrict__ W,
                                          const float* __restrict__ bias,
                                          float* __restrict__ Yext,
                                          int m0, int n0) {
    __shared__ uint32_t As[2][2048];
    __shared__ uint32_t Bs[2][16 * GBS];

    const int tid = threadIdx.x;
    const int w = tid >> 5, lane = tid & 31;
    const int wm = w & 1, wn = w >> 1;
    const int g = lane >> 2, tg = lane & 3;

    const int ar = tid & 127, ag2 = tid >> 7;
    const int br = tid >> 4, bc = (tid & 15) * 8;

    float acc[4][4][4];
#pragma unroll
    for (int mt = 0; mt < 4; mt++)
#pragma unroll
        for (int nt = 0; nt < 4; nt++)
#pragma unroll
            for (int i = 0; i < 4; i++) acc[mt][nt][i] = 0.f;

    {
        float4 a0r = *reinterpret_cast<const float4*>(&X[(size_t)(m0 + ar) * DMODEL + ag2 * 8]);
        float4 a1r = *reinterpret_cast<const float4*>(&X[(size_t)(m0 + ar) * DMODEL + ag2 * 8 + 4]);
        float4 b0r = *reinterpret_cast<const float4*>(&W[(size_t)br * DMODEL + n0 + bc]);
        float4 b1r = *reinterpret_cast<const float4*>(&W[(size_t)br * DMODEL + n0 + bc + 4]);
        uint4 p0, p1;
        pack8(a0r, a1r, p0, p1);
        *reinterpret_cast<uint4*>(&As[0][ag2 * 1024 + ar * 8]) = p0;
        *reinterpret_cast<uint4*>(&As[0][ag2 * 1024 + ar * 8 + 4]) = p1;
        uint4 t0 = {f2tf32(b0r.x), f2tf32(b0r.y), f2tf32(b0r.z), f2tf32(b0r.w)};
        uint4 t1 = {f2tf32(b1r.x), f2tf32(b1r.y), f2tf32(b1r.z), f2tf32(b1r.w)};
        *reinterpret_cast<uint4*>(&Bs[0][br * GBS + bc]) = t0;
        *reinterpret_cast<uint4*>(&Bs[0][br * GBS + bc + 4]) = t1;
    }

#pragma unroll 1
    for (int c = 0; c < 64; c++) {
        const int st = c & 1;
        __syncthreads();

        float4 a0r, a1r, b0r, b1r;
        const bool more = (c + 1 < 64);
        if (more) {
            int k0 = (c + 1) * 16;
            a0r = *reinterpret_cast<const float4*>(&X[(size_t)(m0 + ar) * DMODEL + k0 + ag2 * 8]);
            a1r = *reinterpret_cast<const float4*>(&X[(size_t)(m0 + ar) * DMODEL + k0 + ag2 * 8 + 4]);
            b0r = *reinterpret_cast<const float4*>(&W[(size_t)(k0 + br) * DMODEL + n0 + bc]);
            b1r = *reinterpret_cast<const float4*>(&W[(size_t)(k0 + br) * DMODEL + n0 + bc + 4]);
        }

        const uint32_t* Ac = As[st];
        const uint32_t* Bc = Bs[st];
#pragma unroll
        for (int kg = 0; kg < 2; kg++) {
            uint32_t a[4][4], bf[4][2];
#pragma unroll
            for (int mt = 0; mt < 4; mt++) {
                int mm = wm * 64 + mt * 16 + g;
                uint2 lo = *reinterpret_cast<const uint2*>(&Ac[kg * 1024 + mm * 8 + 2 * tg]);
                uint2 hi = *reinterpret_cast<const uint2*>(&Ac[kg * 1024 + (mm + 8) * 8 + 2 * tg]);
                a[mt][0] = lo.x; a[mt][1] = hi.x; a[mt][2] = lo.y; a[mt][3] = hi.y;
            }
#pragma unroll
            for (int nt = 0; nt < 4; nt++) {
                int nn = wn * 32 + nt * 8 + g;
                bf[nt][0] = Bc[(kg * 8 + tg) * GBS + nn];
                bf[nt][1] = Bc[(kg * 8 + tg + 4) * GBS + nn];
            }
#pragma unroll
            for (int mt = 0; mt < 4; mt++)
#pragma unroll
                for (int nt = 0; nt < 4; nt++)
                    mma_tf32(acc[mt][nt], a[mt][0], a[mt][1], a[mt][2], a[mt][3],
                             bf[nt][0], bf[nt][1]);
        }

        if (more) {
            const int st2 = st ^ 1;
            uint4 p0, p1;
            pack8(a0r, a1r, p0, p1);
            *reinterpret_cast<uint4*>(&As[st2][ag2 * 1024 + ar * 8]) = p0;
            *reinterpret_cast<uint4*>(&As[st2][ag2 * 1024 + ar * 8 + 4]) = p1;
            uint4 t0 = {f2tf32(b0r.x), f2tf32(b0r.y), f2tf32(b0r.z), f2tf32(b0r.w)};
            uint4 t1 = {f2tf32(b1r.x), f2tf32(b1r.y), f2tf32(b1r.z), f2tf32(b1r.w)};
            *reinterpret_cast<uint4*>(&Bs[st2][br * GBS + bc]) = t0;
            *reinterpret_cast<uint4*>(&Bs[st2][br * GBS + bc + 4]) = t1;
        }
    }

    // epilogue
    const int pkl0 = ((2 * tg) & 3) * 2 + ((2 * tg) >> 2);
    const int pkl1 = ((2 * tg + 1) & 3) * 2 + ((2 * tg + 1) >> 2);
#pragma unroll
    for (int nt = 0; nt < 4; nt++) {
        int n = n0 + wn * 32 + nt * 8 + tg * 2;
        float bi0 = __ldg(&bias[n]), bi1 = __ldg(&bias[n + 1]);
#pragma unroll
        for (int mt = 0; mt < 4; mt++) {
#pragma unroll
            for (int half = 0; half < 2; half++) {
                int m = m0 + wm * 64 + mt * 16 + g + half * 8;
                float v0 = acc[mt][nt][half * 2 + 0] + bi0;
                float v1 = acc[mt][nt][half * 2 + 1] + bi1;
                if (MODE == 3) {
                    Yext[(size_t)m * DMODEL + n] = v0;
                    Yext[(size_t)m * DMODEL + n + 1] = v1;
                } else {
                    int b = m >> 11, s = m & 2047;
                    int h = n >> 6, d = n & 63;
                    size_t base = (((size_t)(b * HEADS + h) * SEQ + s) * DHEAD);
                    if (MODE == 0) {
                        g_q[base + (d & ~7) + pkl0] = f2tf32(v0 * QSC);
                        g_q[base + (d & ~7) + pkl1] = f2tf32(v1 * QSC);
                    } else if (MODE == 1) {
                        g_k[base + (d & ~7) + pkl0] = f2tf32(v0);
                        g_k[base + (d & ~7) + pkl1] = f2tf32(v1);
                    } else {
                        float2 o = {__uint_as_float(f2tf32(v0)),
                                    __uint_as_float(f2tf32(v1))};
                        *reinterpret_cast<float2*>(&g_v[base + d]) = o;
                    }
                }
            }
        }
    }
}

// fused Q/K/V projections: blockIdx.z selects which
__global__ __launch_bounds__(256, 2) void gemm_qkv_kernel(
    const float* __restrict__ query, const float* __restrict__ key_,
    const float* __restrict__ value,
    const float* __restrict__ Wq, const float* __restrict__ bq,
    const float* __restrict__ Wk, const float* __restrict__ bk,
    const float* __restrict__ Wv, const float* __restrict__ bv) {
    const int mode = blockIdx.z;
    const int m0 = blockIdx.y * 128, n0 = blockIdx.x * 128;
    if (mode == 0)      gemm_body<0>(query, Wq, bq, nullptr, m0, n0);
    else if (mode == 1) gemm_body<1>(key_,  Wk, bk, nullptr, m0, n0);
    else                gemm_body<2>(value, Wv, bv, nullptr, m0, n0);
}

// output projection
__global__ __launch_bounds__(256, 2) void gemm_o_kernel(
    const float* __restrict__ Wo, const float* __restrict__ bo,
    float* __restrict__ out) {
    gemm_body<3>(g_ctx, Wo, bo, out, blockIdx.y * 128, blockIdx.x * 128);
}

// ======== one-pass attention (R10 config), cp.async staging of prepacked data
#define QT 64
#define CH 128
#define QSs 72
#define KSs 72
#define VSs 72
#define PSs 136
// words: Qs 64*72=4608; Ks 128*72=9216 (aliased as Ps 64*136=8704); Vs 9216; stats 320
#define ATTN_SMEM_U32 (4608 + 9216 + 9216 + 320)

__global__ __launch_bounds__(256, 2) void attn_kernel(float* __restrict__ attn_out) {
    extern __shared__ uint32_t smem_u[];
    uint32_t* Qs = smem_u;
    uint32_t* Ks = Qs + 4608;
    uint32_t* Vs = Ks + 9216;
    float* lbuf = reinterpret_cast<float*>(Vs + 9216);   // [4][64]
    float* smI = lbuf + 256;                             // [64]

    const int tid = threadIdx.x;
    const int w = tid >> 5, lane = tid & 31;
    const int wm = w & 1, wn = w >> 1;
    const int g = lane >> 2, tg = lane & 3;

    const int q0 = blockIdx.x * QT;
    const int h = blockIdx.y, b = blockIdx.z;
    const int bh = b * HEADS + h;

    const uint32_t* qh = g_q + (size_t)bh * SEQ * DHEAD;
    const uint32_t* kh = g_k + (size_t)bh * SEQ * DHEAD;
    const float* vh = g_v + (size_t)bh * SEQ * DHEAD;
    float* arow = attn_out + (size_t)bh * SEQ * SEQ + (size_t)q0 * SEQ;

    const uint32_t qsa = (uint32_t)__cvta_generic_to_shared(Qs);
    const uint32_t ksa = (uint32_t)__cvta_generic_to_shared(Ks);
    const uint32_t vsa = (uint32_t)__cvta_generic_to_shared(Vs);

    // ---- stage Q (already scaled+packed): 64 rows x 16 16B-chunks = 1024 jobs
#pragma unroll
    for (int j = 0; j < 4; j++) {
        int id = j * 256 + tid;
        int r = id >> 4, q = id & 15;
        cp16(qsa + (uint32_t)(r * QSs + q * 4) * 4, qh + (size_t)(q0 + r) * DHEAD + q * 4);
    }
    // (committed together with chunk 0's K/V below)

    const int rA0 = wm * 32 + g;    // + mt*16, + 8 for high half
    const int kc0 = wn * 32;        // this warp's 32-key slice
    const int vc0 = wn * 16;

    uint32_t* Ps = Ks;              // packed P' tile aliases K buffer
    const int pk0 = ((2 * tg) & 3) * 2 + ((2 * tg) >> 2);
    const int pk1 = ((2 * tg + 1) & 3) * 2 + ((2 * tg + 1) >> 2);

    float lacc[4];
#pragma unroll
    for (int i = 0; i < 4; i++) lacc[i] = 0.f;
    float oacc[2][2][4];
#pragma unroll
    for (int mt = 0; mt < 2; mt++)
#pragma unroll
        for (int nt = 0; nt < 2; nt++)
#pragma unroll
            for (int i = 0; i < 4; i++) oacc[mt][nt][i] = 0.f;

    for (int c = 0; c < SEQ / CH; c++) {
        const int kb = c * CH;
        // ---- stage K + V via cp.async: 128 rows x 16 chunks each = 2048 jobs
#pragma unroll
        for (int j = 0; j < 8; j++) {
            int id = j * 256 + tid;
            int r = id >> 4, q = id & 15;
            cp16(ksa + (uint32_t)(r * KSs + q * 4) * 4, kh + (size_t)(kb + r) * DHEAD + q * 4);
            cp16(vsa + (uint32_t)(r * VSs + q * 4) * 4, vh + (size_t)(kb + r) * DHEAD + q * 4);
        }
        CP_COMMIT();
        CP_WAIT0();
        __syncthreads();

        // S = Q @ K^T
        float sacc[2][4][4];
#pragma unroll
        for (int mt = 0; mt < 2; mt++)
#pragma unroll
            for (int nt = 0; nt < 4; nt++)
#pragma unroll
                for (int i = 0; i < 4; i++) sacc[mt][nt][i] = 0.f;
#pragma unroll
        for (int s = 0; s < 8; s++) {
            uint32_t a[2][4];
#pragma unroll
            for (int mt = 0; mt < 2; mt++) {
                int rr = rA0 + mt * 16;
                uint2 lo = *reinterpret_cast<uint2*>(&Qs[rr * QSs + s * 8 + 2 * tg]);
                uint2 hi = *reinterpret_cast<uint2*>(&Qs[(rr + 8) * QSs + s * 8 + 2 * tg]);
                a[mt][0] = lo.x; a[mt][1] = hi.x; a[mt][2] = lo.y; a[mt][3] = hi.y;
            }
#pragma unroll
            for (int nt = 0; nt < 4; nt++) {
                int kr = kc0 + nt * 8 + g;
                uint2 bb = *reinterpret_cast<uint2*>(&Ks[kr * KSs + s * 8 + 2 * tg]);
                mma_tf32(sacc[0][nt], a[0][0], a[0][1], a[0][2], a[0][3], bb.x, bb.y);
                mma_tf32(sacc[1][nt], a[1][0], a[1][1], a[1][2], a[1][3], bb.x, bb.y);
            }
        }
        __syncthreads();   // K reads done before Ps (=Ks) is overwritten

        // P' = exp2(S) : row sums, unnormalized attn write, pack to Ps
#pragma unroll
        for (int mt = 0; mt < 2; mt++) {
            int r0_ = rA0 + mt * 16, r1_ = r0_ + 8;
#pragma unroll
            for (int nt = 0; nt < 4; nt++) {
                int gbase = kc0 + nt * 8;
                float p0 = ex2f(sacc[mt][nt][0]);
                float p1 = ex2f(sacc[mt][nt][1]);
                float p2 = ex2f(sacc[mt][nt][2]);
                float p3 = ex2f(sacc[mt][nt][3]);
                lacc[mt * 2]     += p0 + p1;
                lacc[mt * 2 + 1] += p2 + p3;
                float2 w0 = {p0, p1}, w1 = {p2, p3};
                *reinterpret_cast<float2*>(&arow[(size_t)r0_ * SEQ + kb + gbase + 2 * tg]) = w0;
                *reinterpret_cast<float2*>(&arow[(size_t)r1_ * SEQ + kb + gbase + 2 * tg]) = w1;
                Ps[r0_ * PSs + gbase + pk0] = f2tf32(p0);
                Ps[r0_ * PSs + gbase + pk1] = f2tf32(p1);
                Ps[r1_ * PSs + gbase + pk0] = f2tf32(p2);
                Ps[r1_ * PSs + gbase + pk1] = f2tf32(p3);
            }
        }
        __syncthreads();

        // O' += P' @ V
#pragma unroll
        for (int kg = 0; kg < 16; kg++) {
            uint32_t pa[2][4];
#pragma unroll
            for (int mt = 0; mt < 2; mt++) {
                int rr = rA0 + mt * 16;
                uint2 lo = *reinterpret_cast<uint2*>(&Ps[rr * PSs + kg * 8 + 2 * tg]);
                uint2 hi = *reinterpret_cast<uint2*>(&Ps[(rr + 8) * PSs + kg * 8 + 2 * tg]);
                pa[mt][0] = lo.x; pa[mt][1] = hi.x; pa[mt][2] = lo.y; pa[mt][3] = hi.y;
            }
#pragma unroll
            for (int nt = 0; nt < 2; nt++) {
                int vcol = vc0 + nt * 8 + g;
                uint32_t b0 = Vs[(kg * 8 + tg) * VSs + vcol];
                uint32_t b1 = Vs[(kg * 8 + tg + 4) * VSs + vcol];
                mma_tf32(oacc[0][nt], pa[0][0], pa[0][1], pa[0][2], pa[0][3], b0, b1);
                mma_tf32(oacc[1][nt], pa[1][0], pa[1][1], pa[1][2], pa[1][3], b0, b1);
            }
        }
        __syncthreads();   // Ps/Vs reads done before next chunk's staging
    }

    // ---- reduce l: quad shuffle then across 4 n-warps via smem ----
#pragma unroll
    for (int i = 0; i < 4; i++) {
        lacc[i] += __shfl_xor_sync(0xffffffffu, lacc[i], 1);
        lacc[i] += __shfl_xor_sync(0xffffffffu, lacc[i], 2);
    }
    if (tg == 0) {
#pragma unroll
        for (int mt = 0; mt < 2; mt++)
#pragma unroll
            for (int hf = 0; hf < 2; hf++)
                lbuf[wn * 64 + rA0 + mt * 16 + hf * 8] = lacc[mt * 2 + hf];
    }
    __syncthreads();
    if (tid < 64)
        smI[tid] = 1.f / (lbuf[tid] + lbuf[64 + tid] + lbuf[128 + tid] + lbuf[192 + tid]);
    __syncthreads();

    // ---- write context O = O'/l (head-interleaved) ----
#pragma unroll
    for (int mt = 0; mt < 2; mt++) {
        int r0_ = rA0 + mt * 16, r1_ = r0_ + 8;
        float I0 = smI[r0_], I1 = smI[r1_];
#pragma unroll
        for (int nt = 0; nt < 2; nt++) {
            int cc = h * DHEAD + vc0 + nt * 8 + tg * 2;
            float2 o0 = {oacc[mt][nt][0] * I0, oacc[mt][nt][1] * I0};
            float2 o1 = {oacc[mt][nt][2] * I1, oacc[mt][nt][3] * I1};
            *reinterpret_cast<float2*>(&g_ctx[((size_t)(b * SEQ + q0 + r0_)) * DMODEL + cc]) = o0;
            *reinterpret_cast<float2*>(&g_ctx[((size_t)(b * SEQ + q0 + r1_)) * DMODEL + cc]) = o1;
        }
    }

    // ---- rescale this CTA's attn rows: 64 rows x 512 float4 ----
    float4* af4 = reinterpret_cast<float4*>(arow);
#pragma unroll 4
    for (int j = 0; j < 128; j++) {
        int id = j * 256 + tid;
        int r = id >> 9, cc = id & 511;
        float I = smI[r];
        float4 f = af4[r * 512 + cc];
        f.x *= I; f.y *= I; f.z *= I; f.w *= I;
        af4[r * 512 + cc] = f;
    }
}

// ---------------- launch ----------------
extern "C" void kernel_launch(void* const* d_in, const int* in_sizes, int n_in,
                              void* d_out, int out_size) {
    const float* query = (const float*)d_in[0];
    const float* key   = (const float*)d_in[1];
    const float* value = (const float*)d_in[2];
    const float* Wq = (const float*)d_in[3];
    const float* bq = (const float*)d_in[4];
    const float* Wk = (const float*)d_in[5];
    const float* bk = (const float*)d_in[6];
    const float* Wv = (const float*)d_in[7];
    const float* bv = (const float*)d_in[8];
    const float* Wo = (const float*)d_in[9];
    const float* bo = (const float*)d_in[10];

    float* out = (float*)d_out;
    float* attn = out + OUT_ELEMS;

    static bool attr_set = false;
    if (!attr_set) {
        cudaFuncSetAttribute(attn_kernel, cudaFuncAttributeMaxDynamicSharedMemorySize,
                             ATTN_SMEM_U32 * 4);
        attr_set = true;
    }

    dim3 ggrid(DMODEL / 128, (BATCH * SEQ) / 128, 3);
    gemm_qkv_kernel<<<ggrid, 256>>>(query, key, value, Wq, bq, Wk, bk, Wv, bv);

    dim3 agrid(SEQ / QT, HEADS, BATCH);
    attn_kernel<<<agrid, 256, ATTN_SMEM_U32 * 4>>>(attn);

    dim3 ogrid(DMODEL / 128, (BATCH * SEQ) / 128);
    gemm_o_kernel<<<ogrid, 256>>>(Wo, bo, out);
}

// round 14
// speedup vs baseline: 1.1260x; 1.0137x over previous
#include <cuda_runtime.h>
#include <cuda_bf16.h>
#include <cstdint>

// Problem constants
#define BATCH 2
#define HEADS 16
#define SEQ   2048
#define DMODEL 1024
#define DHEAD 64
#define OUT_ELEMS (BATCH * SEQ * DMODEL)  // 4,194,304

// ---------------- scratch (device globals: allocation-free) ----------------
// g_q: tf32 bits, pre-scaled by 0.125*log2(e), k-pair-packed within 8-groups
// g_k: tf32 bits, k-pair-packed within 8-groups
// g_v: tf32-rounded floats, plain layout
__device__ uint32_t g_q[BATCH * HEADS * SEQ * DHEAD];
__device__ uint32_t g_k[BATCH * HEADS * SEQ * DHEAD];
__device__ float    g_v[BATCH * HEADS * SEQ * DHEAD];
__device__ float    g_ctx[BATCH * SEQ * DMODEL];

#define QSC (0.125f * 1.4426950408889634f)

// ---------------- helpers ----------------
__device__ __forceinline__ uint32_t f2tf32(float x) {
    uint32_t r;
    asm("cvt.rna.tf32.f32 %0, %1;" : "=r"(r) : "f"(x));
    return r;
}
__device__ __forceinline__ float ex2f(float x) {
    float r;
    asm("ex2.approx.f32 %0, %1;" : "=f"(r) : "f"(x));
    return r;
}

__device__ __forceinline__ void mma_tf32(float c[4],
                                         uint32_t a0, uint32_t a1, uint32_t a2, uint32_t a3,
                                         uint32_t b0, uint32_t b1) {
    asm volatile(
        "mma.sync.aligned.m16n8k8.row.col.f32.tf32.tf32.f32 "
        "{%0,%1,%2,%3}, {%4,%5,%6,%7}, {%8,%9}, {%0,%1,%2,%3};"
        : "+f"(c[0]), "+f"(c[1]), "+f"(c[2]), "+f"(c[3])
        : "r"(a0), "r"(a1), "r"(a2), "r"(a3), "r"(b0), "r"(b1));
}

// pack order within an 8-wide k-group: word positions hold cols [0,4,1,5,2,6,3,7]
__device__ __forceinline__ void pack8(const float4& f0, const float4& f1,
                                      uint4& o0, uint4& o1) {
    o0.x = f2tf32(f0.x); o0.y = f2tf32(f1.x); o0.z = f2tf32(f0.y); o0.w = f2tf32(f1.y);
    o1.x = f2tf32(f0.z); o1.y = f2tf32(f1.z); o1.z = f2tf32(f0.w); o1.w = f2tf32(f1.w);
}

__device__ __forceinline__ void cp16(uint32_t smem_addr, const void* gptr) {
    asm volatile("cp.async.cg.shared.global [%0], [%1], 16;"
                 :: "r"(smem_addr), "l"(gptr));
}
#define CP_COMMIT() asm volatile("cp.async.commit_group;" ::: "memory")
#define CP_WAIT0()  asm volatile("cp.async.wait_group 0;" ::: "memory")

// ================= GEMM core: double-buffered SMEM, 1 sync/chunk =============
// MODE: 0=Q (packed+scaled), 1=K (packed), 2=V (rounded), 3=output (plain)
#define GBS 136

template <int MODE>
__device__ __forceinline__ void gemm_body(const float* __restrict__ X,
                                          const float* __restrict__ W,
                                          const float* __restrict__ bias,
                                          float* __restrict__ Yext,
                                          int m0, int n0) {
    __shared__ uint32_t As[2][2048];
    __shared__ uint32_t Bs[2][16 * GBS];

    const int tid = threadIdx.x;
    const int w = tid >> 5, lane = tid & 31;
    const int wm = w & 1, wn = w >> 1;
    const int g = lane >> 2, tg = lane & 3;

    const int ar = tid & 127, ag2 = tid >> 7;
    const int br = tid >> 4, bc = (tid & 15) * 8;

    float acc[4][4][4];
#pragma unroll
    for (int mt = 0; mt < 4; mt++)
#pragma unroll
        for (int nt = 0; nt < 4; nt++)
#pragma unroll
            for (int i = 0; i < 4; i++) acc[mt][nt][i] = 0.f;

    {
        float4 a0r = *reinterpret_cast<const float4*>(&X[(size_t)(m0 + ar) * DMODEL + ag2 * 8]);
        float4 a1r = *reinterpret_cast<const float4*>(&X[(size_t)(m0 + ar) * DMODEL + ag2 * 8 + 4]);
        float4 b0r = *reinterpret_cast<const float4*>(&W[(size_t)br * DMODEL + n0 + bc]);
        float4 b1r = *reinterpret_cast<const float4*>(&W[(size_t)br * DMODEL + n0 + bc + 4]);
        uint4 p0, p1;
        pack8(a0r, a1r, p0, p1);
        *reinterpret_cast<uint4*>(&As[0][ag2 * 1024 + ar * 8]) = p0;
        *reinterpret_cast<uint4*>(&As[0][ag2 * 1024 + ar * 8 + 4]) = p1;
        uint4 t0 = {f2tf32(b0r.x), f2tf32(b0r.y), f2tf32(b0r.z), f2tf32(b0r.w)};
        uint4 t1 = {f2tf32(b1r.x), f2tf32(b1r.y), f2tf32(b1r.z), f2tf32(b1r.w)};
        *reinterpret_cast<uint4*>(&Bs[0][br * GBS + bc]) = t0;
        *reinterpret_cast<uint4*>(&Bs[0][br * GBS + bc + 4]) = t1;
    }

#pragma unroll 1
    for (int c = 0; c < 64; c++) {
        const int st = c & 1;
        __syncthreads();

        float4 a0r, a1r, b0r, b1r;
        const bool more = (c + 1 < 64);
        if (more) {
            int k0 = (c + 1) * 16;
            a0r = *reinterpret_cast<const float4*>(&X[(size_t)(m0 + ar) * DMODEL + k0 + ag2 * 8]);
            a1r = *reinterpret_cast<const float4*>(&X[(size_t)(m0 + ar) * DMODEL + k0 + ag2 * 8 + 4]);
            b0r = *reinterpret_cast<const float4*>(&W[(size_t)(k0 + br) * DMODEL + n0 + bc]);
            b1r = *reinterpret_cast<const float4*>(&W[(size_t)(k0 + br) * DMODEL + n0 + bc + 4]);
        }

        const uint32_t* Ac = As[st];
        const uint32_t* Bc = Bs[st];
#pragma unroll
        for (int kg = 0; kg < 2; kg++) {
            uint32_t a[4][4], bf[4][2];
#pragma unroll
            for (int mt = 0; mt < 4; mt++) {
                int mm = wm * 64 + mt * 16 + g;
                uint2 lo = *reinterpret_cast<const uint2*>(&Ac[kg * 1024 + mm * 8 + 2 * tg]);
                uint2 hi = *reinterpret_cast<const uint2*>(&Ac[kg * 1024 + (mm + 8) * 8 + 2 * tg]);
                a[mt][0] = lo.x; a[mt][1] = hi.x; a[mt][2] = lo.y; a[mt][3] = hi.y;
            }
#pragma unroll
            for (int nt = 0; nt < 4; nt++) {
                int nn = wn * 32 + nt * 8 + g;
                bf[nt][0] = Bc[(kg * 8 + tg) * GBS + nn];
                bf[nt][1] = Bc[(kg * 8 + tg + 4) * GBS + nn];
            }
#pragma unroll
            for (int mt = 0; mt < 4; mt++)
#pragma unroll
                for (int nt = 0; nt < 4; nt++)
                    mma_tf32(acc[mt][nt], a[mt][0], a[mt][1], a[mt][2], a[mt][3],
                             bf[nt][0], bf[nt][1]);
        }

        if (more) {
            const int st2 = st ^ 1;
            uint4 p0, p1;
            pack8(a0r, a1r, p0, p1);
            *reinterpret_cast<uint4*>(&As[st2][ag2 * 1024 + ar * 8]) = p0;
            *reinterpret_cast<uint4*>(&As[st2][ag2 * 1024 + ar * 8 + 4]) = p1;
            uint4 t0 = {f2tf32(b0r.x), f2tf32(b0r.y), f2tf32(b0r.z), f2tf32(b0r.w)};
            uint4 t1 = {f2tf32(b1r.x), f2tf32(b1r.y), f2tf32(b1r.z), f2tf32(b1r.w)};
            *reinterpret_cast<uint4*>(&Bs[st2][br * GBS + bc]) = t0;
            *reinterpret_cast<uint4*>(&Bs[st2][br * GBS + bc + 4]) = t1;
        }
    }

    // epilogue
    const int pkl0 = ((2 * tg) & 3) * 2 + ((2 * tg) >> 2);
    const int pkl1 = ((2 * tg + 1) & 3) * 2 + ((2 * tg + 1) >> 2);
#pragma unroll
    for (int nt = 0; nt < 4; nt++) {
        int n = n0 + wn * 32 + nt * 8 + tg * 2;
        float bi0 = __ldg(&bias[n]), bi1 = __ldg(&bias[n + 1]);
#pragma unroll
        for (int mt = 0; mt < 4; mt++) {
#pragma unroll
            for (int half = 0; half < 2; half++) {
                int m = m0 + wm * 64 + mt * 16 + g + half * 8;
                float v0 = acc[mt][nt][half * 2 + 0] + bi0;
                float v1 = acc[mt][nt][half * 2 + 1] + bi1;
                if (MODE == 3) {
                    Yext[(size_t)m * DMODEL + n] = v0;
                    Yext[(size_t)m * DMODEL + n + 1] = v1;
                } else {
                    int b = m >> 11, s = m & 2047;
                    int h = n >> 6, d = n & 63;
                    size_t base = (((size_t)(b * HEADS + h) * SEQ + s) * DHEAD);
                    if (MODE == 0) {
                        g_q[base + (d & ~7) + pkl0] = f2tf32(v0 * QSC);
                        g_q[base + (d & ~7) + pkl1] = f2tf32(v1 * QSC);
                    } else if (MODE == 1) {
                        g_k[base + (d & ~7) + pkl0] = f2tf32(v0);
                        g_k[base + (d & ~7) + pkl1] = f2tf32(v1);
                    } else {
                        float2 o = {__uint_as_float(f2tf32(v0)),
                                    __uint_as_float(f2tf32(v1))};
                        *reinterpret_cast<float2*>(&g_v[base + d]) = o;
                    }
                }
            }
        }
    }
}

// fused Q/K/V projections: blockIdx.z selects which
__global__ __launch_bounds__(256, 2) void gemm_qkv_kernel(
    const float* __restrict__ query, const float* __restrict__ key_,
    const float* __restrict__ value,
    const float* __restrict__ Wq, const float* __restrict__ bq,
    const float* __restrict__ Wk, const float* __restrict__ bk,
    const float* __restrict__ Wv, const float* __restrict__ bv) {
    const int mode = blockIdx.z;
    const int m0 = blockIdx.y * 128, n0 = blockIdx.x * 128;
    if (mode == 0)      gemm_body<0>(query, Wq, bq, nullptr, m0, n0);
    else if (mode == 1) gemm_body<1>(key_,  Wk, bk, nullptr, m0, n0);
    else                gemm_body<2>(value, Wv, bv, nullptr, m0, n0);
}

// output projection
__global__ __launch_bounds__(256, 2) void gemm_o_kernel(
    const float* __restrict__ Wo, const float* __restrict__ bo,
    float* __restrict__ out) {
    gemm_body<3>(g_ctx, Wo, bo, out, blockIdx.y * 128, blockIdx.x * 128);
}

// ======== one-pass attention: CH=64, separate Ps, 3 CTAs/SM ==========
// grid (SEQ/64, HEADS, BATCH), 256 threads, warps 2(m)x4(n).
// Prepacked operands; cp.async staging; 3 syncs per chunk.
#define QT 64
#define CH 64
#define NCH (SEQ / CH)      // 32
#define QSs 72
#define KSs 72
#define VSs 72
#define PSs 72
// words: Qs 64*72=4608; Ks 64*72=4608; Vs 4608; Ps 4608; stats 320  -> 75KB
#define ATTN_SMEM_U32 (4608 * 4 + 320)

__global__ __launch_bounds__(256, 3) void attn_kernel(float* __restrict__ attn_out) {
    extern __shared__ uint32_t smem_u[];
    uint32_t* Qs = smem_u;
    uint32_t* Ks = Qs + 4608;
    uint32_t* Vs = Ks + 4608;
    uint32_t* Ps = Vs + 4608;
    float* lbuf = reinterpret_cast<float*>(Ps + 4608);   // [4][64]
    float* smI = lbuf + 256;                             // [64]

    const int tid = threadIdx.x;
    const int w = tid >> 5, lane = tid & 31;
    const int wm = w & 1, wn = w >> 1;
    const int g = lane >> 2, tg = lane & 3;

    const int q0 = blockIdx.x * QT;
    const int h = blockIdx.y, b = blockIdx.z;
    const int bh = b * HEADS + h;

    const uint32_t* qh = g_q + (size_t)bh * SEQ * DHEAD;
    const uint32_t* kh = g_k + (size_t)bh * SEQ * DHEAD;
    const float* vh = g_v + (size_t)bh * SEQ * DHEAD;
    float* arow = attn_out + (size_t)bh * SEQ * SEQ + (size_t)q0 * SEQ;

    const uint32_t qsa = (uint32_t)__cvta_generic_to_shared(Qs);
    const uint32_t ksa = (uint32_t)__cvta_generic_to_shared(Ks);
    const uint32_t vsa = (uint32_t)__cvta_generic_to_shared(Vs);

    // ---- stage Q (already scaled+packed): 64 rows x 16 16B-chunks = 1024 jobs
#pragma unroll
    for (int j = 0; j < 4; j++) {
        int id = j * 256 + tid;
        int r = id >> 4, q = id & 15;
        cp16(qsa + (uint32_t)(r * QSs + q * 4) * 4, qh + (size_t)(q0 + r) * DHEAD + q * 4);
    }
    // (committed together with chunk 0's K/V below)

    const int rA0 = wm * 32 + g;    // + mt*16, + 8 for high half
    const int kc0 = wn * 16;        // this warp's 16-key slice of the 64-key chunk
    const int vc0 = wn * 16;

    const int pk0 = ((2 * tg) & 3) * 2 + ((2 * tg) >> 2);
    const int pk1 = ((2 * tg + 1) & 3) * 2 + ((2 * tg + 1) >> 2);

    float lacc[4];
#pragma unroll
    for (int i = 0; i < 4; i++) lacc[i] = 0.f;
    float oacc[2][2][4];
#pragma unroll
    for (int mt = 0; mt < 2; mt++)
#pragma unroll
        for (int nt = 0; nt < 2; nt++)
#pragma unroll
            for (int i = 0; i < 4; i++) oacc[mt][nt][i] = 0.f;

    for (int c = 0; c < NCH; c++) {
        const int kb = c * CH;
        // ---- stage K + V: 64 rows x 16 chunks each = 1024 jobs each ----
#pragma unroll
        for (int j = 0; j < 4; j++) {
            int id = j * 256 + tid;
            int r = id >> 4, q = id & 15;
            cp16(ksa + (uint32_t)(r * KSs + q * 4) * 4, kh + (size_t)(kb + r) * DHEAD + q * 4);
            cp16(vsa + (uint32_t)(r * VSs + q * 4) * 4, vh + (size_t)(kb + r) * DHEAD + q * 4);
        }
        CP_COMMIT();
        CP_WAIT0();
        __syncthreads();                       // sync 1: K/V (and Q on c=0) ready

        // ---- S = Q @ K^T  (warp: 32 q-rows x 16 keys) ----
        float sacc[2][2][4];
#pragma unroll
        for (int mt = 0; mt < 2; mt++)
#pragma unroll
            for (int nt = 0; nt < 2; nt++)
#pragma unroll
                for (int i = 0; i < 4; i++) sacc[mt][nt][i] = 0.f;

#pragma unroll
        for (int s = 0; s < 8; s++) {
            uint32_t a[2][4];
#pragma unroll
            for (int mt = 0; mt < 2; mt++) {
                int rr = rA0 + mt * 16;
                uint2 lo = *reinterpret_cast<uint2*>(&Qs[rr * QSs + s * 8 + 2 * tg]);
                uint2 hi = *reinterpret_cast<uint2*>(&Qs[(rr + 8) * QSs + s * 8 + 2 * tg]);
                a[mt][0] = lo.x; a[mt][1] = hi.x; a[mt][2] = lo.y; a[mt][3] = hi.y;
            }
#pragma unroll
            for (int nt = 0; nt < 2; nt++) {
                int kr = kc0 + nt * 8 + g;
                uint2 bb = *reinterpret_cast<uint2*>(&Ks[kr * KSs + s * 8 + 2 * tg]);
                mma_tf32(sacc[0][nt], a[0][0], a[0][1], a[0][2], a[0][3], bb.x, bb.y);
                mma_tf32(sacc[1][nt], a[1][0], a[1][1], a[1][2], a[1][3], bb.x, bb.y);
            }
        }

        // ---- P' = exp2(S): row sums, unnormalized attn write, pack to Ps ----
        // (no sync needed: Ps is a dedicated buffer, own-warp rows/cols)
#pragma unroll
        for (int mt = 0; mt < 2; mt++) {
            int r0_ = rA0 + mt * 16, r1_ = r0_ + 8;
#pragma unroll
            for (int nt = 0; nt < 2; nt++) {
                int gbase = kc0 + nt * 8;
                float p0 = ex2f(sacc[mt][nt][0]);
                float p1 = ex2f(sacc[mt][nt][1]);
                float p2 = ex2f(sacc[mt][nt][2]);
                float p3 = ex2f(sacc[mt][nt][3]);
                lacc[mt * 2]     += p0 + p1;
                lacc[mt * 2 + 1] += p2 + p3;
                float2 w0 = {p0, p1}, w1 = {p2, p3};
                *reinterpret_cast<float2*>(&arow[(size_t)r0_ * SEQ + kb + gbase + 2 * tg]) = w0;
                *reinterpret_cast<float2*>(&arow[(size_t)r1_ * SEQ + kb + gbase + 2 * tg]) = w1;
                Ps[r0_ * PSs + gbase + pk0] = f2tf32(p0);
                Ps[r0_ * PSs + gbase + pk1] = f2tf32(p1);
                Ps[r1_ * PSs + gbase + pk0] = f2tf32(p2);
                Ps[r1_ * PSs + gbase + pk1] = f2tf32(p3);
            }
        }
        __syncthreads();                       // sync 2: all warps' P ready

        // ---- O' += P' @ V  (warp: 32 rows x 16 v-cols, k over 64 keys) ----
#pragma unroll
        for (int kg = 0; kg < 8; kg++) {
            uint32_t pa[2][4];
#pragma unroll
            for (int mt = 0; mt < 2; mt++) {
                int rr = rA0 + mt * 16;
                uint2 lo = *reinterpret_cast<uint2*>(&Ps[rr * PSs + kg * 8 + 2 * tg]);
                uint2 hi = *reinterpret_cast<uint2*>(&Ps[(rr + 8) * PSs + kg * 8 + 2 * tg]);
                pa[mt][0] = lo.x; pa[mt][1] = hi.x; pa[mt][2] = lo.y; pa[mt][3] = hi.y;
            }
#pragma unroll
            for (int nt = 0; nt < 2; nt++) {
                int vcol = vc0 + nt * 8 + g;
                uint32_t b0 = Vs[(kg * 8 + tg) * VSs + vcol];
                uint32_t b1 = Vs[(kg * 8 + tg + 4) * VSs + vcol];
                mma_tf32(oacc[0][nt], pa[0][0], pa[0][1], pa[0][2], pa[0][3], b0, b1);
                mma_tf32(oacc[1][nt], pa[1][0], pa[1][1], pa[1][2], pa[1][3], b0, b1);
            }
        }
        __syncthreads();                       // sync 3: Ks/Vs/Ps free for next chunk
    }

    // ---- reduce l: quad shuffle then across 4 n-warps via smem ----
#pragma unroll
    for (int i = 0; i < 4; i++) {
        lacc[i] += __shfl_xor_sync(0xffffffffu, lacc[i], 1);
        lacc[i] += __shfl_xor_sync(0xffffffffu, lacc[i], 2);
    }
    if (tg == 0) {
#pragma unroll
        for (int mt = 0; mt < 2; mt++)
#pragma unroll
            for (int hf = 0; hf < 2; hf++)
                lbuf[wn * 64 + rA0 + mt * 16 + hf * 8] = lacc[mt * 2 + hf];
    }
    __syncthreads();
    if (tid < 64)
        smI[tid] = 1.f / (lbuf[tid] + lbuf[64 + tid] + lbuf[128 + tid] + lbuf[192 + tid]);
    __syncthreads();

    // ---- write context O = O'/l (head-interleaved) ----
#pragma unroll
    for (int mt = 0; mt < 2; mt++) {
        int r0_ = rA0 + mt * 16, r1_ = r0_ + 8;
        float I0 = smI[r0_], I1 = smI[r1_];
#pragma unroll
        for (int nt = 0; nt < 2; nt++) {
            int cc = h * DHEAD + vc0 + nt * 8 + tg * 2;
            float2 o0 = {oacc[mt][nt][0] * I0, oacc[mt][nt][1] * I0};
            float2 o1 = {oacc[mt][nt][2] * I1, oacc[mt][nt][3] * I1};
            *reinterpret_cast<float2*>(&g_ctx[((size_t)(b * SEQ + q0 + r0_)) * DMODEL + cc]) = o0;
            *reinterpret_cast<float2*>(&g_ctx[((size_t)(b * SEQ + q0 + r1_)) * DMODEL + cc]) = o1;
        }
    }

    // ---- rescale this CTA's attn rows: 64 rows x 512 float4 ----
    float4* af4 = reinterpret_cast<float4*>(arow);
#pragma unroll 4
    for (int j = 0; j < 128; j++) {
        int id = j * 256 + tid;
        int r = id >> 9, cc = id & 511;
        float I = smI[r];
        float4 f = af4[r * 512 + cc];
        f.x *= I; f.y *= I; f.z *= I; f.w *= I;
        af4[r * 512 + cc] = f;
    }
}

// ---------------- launch ----------------
extern "C" void kernel_launch(void* const* d_in, const int* in_sizes, int n_in,
                              void* d_out, int out_size) {
    const float* query = (const float*)d_in[0];
    const float* key   = (const float*)d_in[1];
    const float* value = (const float*)d_in[2];
    const float* Wq = (const float*)d_in[3];
    const float* bq = (const float*)d_in[4];
    const float* Wk = (const float*)d_in[5];
    const float* bk = (const float*)d_in[6];
    const float* Wv = (const float*)d_in[7];
    const float* bv = (const float*)d_in[8];
    const float* Wo = (const float*)d_in[9];
    const float* bo = (const float*)d_in[10];

    float* out = (float*)d_out;
    float* attn = out + OUT_ELEMS;

    static bool attr_set = false;
    if (!attr_set) {
        cudaFuncSetAttribute(attn_kernel, cudaFuncAttributeMaxDynamicSharedMemorySize,
                             ATTN_SMEM_U32 * 4);
        attr_set = true;
    }

    dim3 ggrid(DMODEL / 128, (BATCH * SEQ) / 128, 3);
    gemm_qkv_kernel<<<ggrid, 256>>>(query, key, value, Wq, bq, Wk, bk, Wv, bv);

    dim3 agrid(SEQ / QT, HEADS, BATCH);
    attn_kernel<<<agrid, 256, ATTN_SMEM_U32 * 4>>>(attn);

    dim3 ogrid(DMODEL / 128, (BATCH * SEQ) / 128);
    gemm_o_kernel<<<ogrid, 256>>>(Wo, bo, out);
}